// round 1
// baseline (speedup 1.0000x reference)
#include <cuda_runtime.h>
#include <math.h>

#define NEGINF -1000000.0f

// Problem constants
#define BATCH 8
#define SEQ   2048
#define EMB   512
#define BSZ   (BATCH * SEQ)   // 16384 rows total

// Scratch: Q, K, V projections (fp32). __device__ globals (no allocs allowed).
__device__ float g_Q[(size_t)BSZ * EMB];
__device__ float g_K[(size_t)BSZ * EMB];
__device__ float g_V[(size_t)BSZ * EMB];

// SGEMM tiling
#define BM 128
#define BN 128
#define BK 16
#define TM 8
#define TN 8
#define PAD 4   // smem row padding to dodge transpose-store bank conflicts

// ---------------------------------------------------------------------------
// Kernel 1: projections. C[M,N] = alpha * A[M,K] @ W[K,N]
//   M = 16384, K = 512, N = 512. gridDim.z picks (Xq,Wq,Q)/(Xk,Wk,K)/(Xv,Wv,V)
// ---------------------------------------------------------------------------
__global__ __launch_bounds__(256)
void proj_kernel(const float* __restrict__ Xq, const float* __restrict__ Xk,
                 const float* __restrict__ Xv, const float* __restrict__ Wq,
                 const float* __restrict__ Wk, const float* __restrict__ Wv,
                 float inv_scale)
{
    const float* A; const float* W; float* C; float alpha;
    int z = blockIdx.z;
    if (z == 0)      { A = Xq; W = Wq; C = g_Q; alpha = inv_scale; }
    else if (z == 1) { A = Xk; W = Wk; C = g_K; alpha = inv_scale; }
    else             { A = Xv; W = Wv; C = g_V; alpha = 1.0f; }

    const int K = 512, N = 512;

    __shared__ float As[BK][BM + PAD];
    __shared__ float Bs[BK][BN + PAD];

    int tid = threadIdx.x;
    int tr = tid >> 4;          // 0..15
    int tc = tid & 15;          // 0..15
    int m0 = blockIdx.y * BM;
    int n0 = blockIdx.x * BN;

    int arow = tid >> 2;            // 0..63
    int acol = (tid & 3) << 2;      // 0,4,8,12
    int brow = tid >> 5;            // 0..7
    int bcol = (tid & 31) << 2;     // 0..124

    float acc[TM][TN];
#pragma unroll
    for (int i = 0; i < TM; i++)
#pragma unroll
        for (int j = 0; j < TN; j++) acc[i][j] = 0.f;

    for (int k0 = 0; k0 < K; k0 += BK) {
#pragma unroll
        for (int p = 0; p < 2; p++) {
            float4 v = *(const float4*)&A[(size_t)(m0 + arow + p * 64) * K + k0 + acol];
            As[acol + 0][arow + p * 64] = v.x;
            As[acol + 1][arow + p * 64] = v.y;
            As[acol + 2][arow + p * 64] = v.z;
            As[acol + 3][arow + p * 64] = v.w;
        }
#pragma unroll
        for (int p = 0; p < 2; p++) {
            *(float4*)&Bs[brow + p * 8][bcol] =
                *(const float4*)&W[(size_t)(k0 + brow + p * 8) * N + n0 + bcol];
        }
        __syncthreads();
#pragma unroll
        for (int kk = 0; kk < BK; kk++) {
            float ra[TM], rb[TN];
            *(float4*)&ra[0] = *(float4*)&As[kk][tr * TM];
            *(float4*)&ra[4] = *(float4*)&As[kk][tr * TM + 4];
            *(float4*)&rb[0] = *(float4*)&Bs[kk][tc * TN];
            *(float4*)&rb[4] = *(float4*)&Bs[kk][tc * TN + 4];
#pragma unroll
            for (int i = 0; i < TM; i++)
#pragma unroll
                for (int j = 0; j < TN; j++)
                    acc[i][j] += ra[i] * rb[j];
        }
        __syncthreads();
    }

#pragma unroll
    for (int i = 0; i < TM; i++) {
#pragma unroll
        for (int j = 0; j < TN; j += 4) {
            float4 v;
            v.x = acc[i][j + 0] * alpha;
            v.y = acc[i][j + 1] * alpha;
            v.z = acc[i][j + 2] * alpha;
            v.w = acc[i][j + 3] * alpha;
            *(float4*)&C[(size_t)(m0 + tr * TM + i) * N + n0 + tc * TN + j] = v;
        }
    }
}

// ---------------------------------------------------------------------------
// Kernel 2: masked scores. logits[b,q,k] = Q[b,q,:] . K[b,k,:], NEGINF where
// mask == 0. Written into the attn_p region of d_out (overwritten by softmax).
//   Per batch: M = N = 2048, K = 512.
// ---------------------------------------------------------------------------
__global__ __launch_bounds__(256)
void scores_kernel(const int* __restrict__ mask, float* __restrict__ out_p)
{
    const int K = 512;
    int b = blockIdx.z;
    const float* Qb = g_Q + (size_t)b * SEQ * EMB;
    const float* Kb = g_K + (size_t)b * SEQ * EMB;
    const int*  Mb  = mask + (size_t)b * SEQ * SEQ;
    float*      Cb  = out_p + (size_t)b * SEQ * SEQ;

    __shared__ float As[BK][BM + PAD];
    __shared__ float Bs[BK][BN + PAD];

    int tid = threadIdx.x;
    int tr = tid >> 4, tc = tid & 15;
    int m0 = blockIdx.y * BM;
    int n0 = blockIdx.x * BN;

    int arow = tid >> 2;
    int acol = (tid & 3) << 2;

    float acc[TM][TN];
#pragma unroll
    for (int i = 0; i < TM; i++)
#pragma unroll
        for (int j = 0; j < TN; j++) acc[i][j] = 0.f;

    for (int k0 = 0; k0 < K; k0 += BK) {
#pragma unroll
        for (int p = 0; p < 2; p++) {
            float4 v = *(const float4*)&Qb[(size_t)(m0 + arow + p * 64) * K + k0 + acol];
            As[acol + 0][arow + p * 64] = v.x;
            As[acol + 1][arow + p * 64] = v.y;
            As[acol + 2][arow + p * 64] = v.z;
            As[acol + 3][arow + p * 64] = v.w;
        }
        // B operand is K-matrix transposed: Bs[k][n] = Kb[n0+n][k0+k]
#pragma unroll
        for (int p = 0; p < 2; p++) {
            float4 v = *(const float4*)&Kb[(size_t)(n0 + arow + p * 64) * K + k0 + acol];
            Bs[acol + 0][arow + p * 64] = v.x;
            Bs[acol + 1][arow + p * 64] = v.y;
            Bs[acol + 2][arow + p * 64] = v.z;
            Bs[acol + 3][arow + p * 64] = v.w;
        }
        __syncthreads();
#pragma unroll
        for (int kk = 0; kk < BK; kk++) {
            float ra[TM], rb[TN];
            *(float4*)&ra[0] = *(float4*)&As[kk][tr * TM];
            *(float4*)&ra[4] = *(float4*)&As[kk][tr * TM + 4];
            *(float4*)&rb[0] = *(float4*)&Bs[kk][tc * TN];
            *(float4*)&rb[4] = *(float4*)&Bs[kk][tc * TN + 4];
#pragma unroll
            for (int i = 0; i < TM; i++)
#pragma unroll
                for (int j = 0; j < TN; j++)
                    acc[i][j] += ra[i] * rb[j];
        }
        __syncthreads();
    }

#pragma unroll
    for (int i = 0; i < TM; i++) {
        size_t roff = (size_t)(m0 + tr * TM + i) * SEQ + n0 + tc * TN;
#pragma unroll
        for (int j = 0; j < TN; j += 4) {
            int4 mv = *(const int4*)&Mb[roff + j];
            float4 v;
            v.x = mv.x ? acc[i][j + 0] : NEGINF;
            v.y = mv.y ? acc[i][j + 1] : NEGINF;
            v.z = mv.z ? acc[i][j + 2] : NEGINF;
            v.w = mv.w ? acc[i][j + 3] : NEGINF;
            *(float4*)&Cb[roff + j] = v;
        }
    }
}

// ---------------------------------------------------------------------------
// Kernel 3: row softmax (in place over attn_p region).
// Masked entries hold NEGINF -> exp underflows to exactly 0 (== softmax*mask),
// except fully-masked rows which must be all-zero.
// One block (256 threads) per row of 2048.
// ---------------------------------------------------------------------------
__global__ __launch_bounds__(256)
void softmax_kernel(float* __restrict__ P)
{
    float* prow = P + (size_t)blockIdx.x * SEQ;
    int tid = threadIdx.x;
    int lane = tid & 31, warp = tid >> 5;
    __shared__ float red[8];

    float4 v0 = ((const float4*)prow)[tid];
    float4 v1 = ((const float4*)prow)[tid + 256];
    float x[8] = {v0.x, v0.y, v0.z, v0.w, v1.x, v1.y, v1.z, v1.w};

    float m = x[0];
#pragma unroll
    for (int i = 1; i < 8; i++) m = fmaxf(m, x[i]);
#pragma unroll
    for (int o = 16; o > 0; o >>= 1) m = fmaxf(m, __shfl_xor_sync(0xFFFFFFFFu, m, o));
    if (lane == 0) red[warp] = m;
    __syncthreads();
    m = red[0];
#pragma unroll
    for (int i = 1; i < 8; i++) m = fmaxf(m, red[i]);

    if (m == NEGINF) {  // fully masked row -> reference gives softmax*mask = 0
        float4 z = make_float4(0.f, 0.f, 0.f, 0.f);
        ((float4*)prow)[tid] = z;
        ((float4*)prow)[tid + 256] = z;
        return;
    }

    float e[8], s = 0.f;
#pragma unroll
    for (int i = 0; i < 8; i++) { e[i] = __expf(x[i] - m); s += e[i]; }
#pragma unroll
    for (int o = 16; o > 0; o >>= 1) s += __shfl_xor_sync(0xFFFFFFFFu, s, o);
    __syncthreads();   // red[] reuse
    if (lane == 0) red[warp] = s;
    __syncthreads();
    s = 0.f;
#pragma unroll
    for (int i = 0; i < 8; i++) s += red[i];
    float inv = 1.0f / s;

    float4 o0 = make_float4(e[0] * inv, e[1] * inv, e[2] * inv, e[3] * inv);
    float4 o1 = make_float4(e[4] * inv, e[5] * inv, e[6] * inv, e[7] * inv);
    ((float4*)prow)[tid] = o0;
    ((float4*)prow)[tid + 256] = o1;
}

// ---------------------------------------------------------------------------
// Kernel 4: z = P @ V per batch. M = 2048, N = 512, K = 2048.
// ---------------------------------------------------------------------------
__global__ __launch_bounds__(256)
void pv_kernel(const float* __restrict__ P, float* __restrict__ out_z)
{
    const int K = SEQ, N = EMB;
    int b = blockIdx.z;
    const float* Ab = P + (size_t)b * SEQ * SEQ;
    const float* Vb = g_V + (size_t)b * SEQ * EMB;
    float*       Cb = out_z + (size_t)b * SEQ * EMB;

    __shared__ float As[BK][BM + PAD];
    __shared__ float Bs[BK][BN + PAD];

    int tid = threadIdx.x;
    int tr = tid >> 4, tc = tid & 15;
    int m0 = blockIdx.y * BM;
    int n0 = blockIdx.x * BN;

    int arow = tid >> 2;
    int acol = (tid & 3) << 2;
    int brow = tid >> 5;
    int bcol = (tid & 31) << 2;

    float acc[TM][TN];
#pragma unroll
    for (int i = 0; i < TM; i++)
#pragma unroll
        for (int j = 0; j < TN; j++) acc[i][j] = 0.f;

    for (int k0 = 0; k0 < K; k0 += BK) {
#pragma unroll
        for (int p = 0; p < 2; p++) {
            float4 v = *(const float4*)&Ab[(size_t)(m0 + arow + p * 64) * K + k0 + acol];
            As[acol + 0][arow + p * 64] = v.x;
            As[acol + 1][arow + p * 64] = v.y;
            As[acol + 2][arow + p * 64] = v.z;
            As[acol + 3][arow + p * 64] = v.w;
        }
#pragma unroll
        for (int p = 0; p < 2; p++) {
            *(float4*)&Bs[brow + p * 8][bcol] =
                *(const float4*)&Vb[(size_t)(k0 + brow + p * 8) * N + n0 + bcol];
        }
        __syncthreads();
#pragma unroll
        for (int kk = 0; kk < BK; kk++) {
            float ra[TM], rb[TN];
            *(float4*)&ra[0] = *(float4*)&As[kk][tr * TM];
            *(float4*)&ra[4] = *(float4*)&As[kk][tr * TM + 4];
            *(float4*)&rb[0] = *(float4*)&Bs[kk][tc * TN];
            *(float4*)&rb[4] = *(float4*)&Bs[kk][tc * TN + 4];
#pragma unroll
            for (int i = 0; i < TM; i++)
#pragma unroll
                for (int j = 0; j < TN; j++)
                    acc[i][j] += ra[i] * rb[j];
        }
        __syncthreads();
    }

#pragma unroll
    for (int i = 0; i < TM; i++) {
#pragma unroll
        for (int j = 0; j < TN; j += 4) {
            float4 v;
            v.x = acc[i][j + 0];
            v.y = acc[i][j + 1];
            v.z = acc[i][j + 2];
            v.w = acc[i][j + 3];
            *(float4*)&Cb[(size_t)(m0 + tr * TM + i) * N + n0 + tc * TN + j] = v;
        }
    }
}

// ---------------------------------------------------------------------------
// Launch. Inputs (metadata order): Xin_q, Xin_k, Xin_v, mask, Wq, Wk, Wv.
// Output: z [8,2048,512] followed by attn_p [8,2048,2048], fp32.
// ---------------------------------------------------------------------------
extern "C" void kernel_launch(void* const* d_in, const int* in_sizes, int n_in,
                              void* d_out, int out_size)
{
    const float* Xq = (const float*)d_in[0];
    const float* Xk = (const float*)d_in[1];
    const float* Xv = (const float*)d_in[2];
    const int*   mk = (const int*)d_in[3];
    const float* Wq = (const float*)d_in[4];
    const float* Wk = (const float*)d_in[5];
    const float* Wv = (const float*)d_in[6];

    float* out_z = (float*)d_out;
    float* out_p = out_z + (size_t)BATCH * SEQ * EMB;

    // 1/512^(1/4): applied to both Q and K -> QK^T / sqrt(512)
    const float inv_scale = 0.21022410381342864f;

    proj_kernel<<<dim3(EMB / BN, BSZ / BM, 3), 256>>>(Xq, Xk, Xv, Wq, Wk, Wv, inv_scale);
    scores_kernel<<<dim3(SEQ / BN, SEQ / BM, BATCH), 256>>>(mk, out_p);
    softmax_kernel<<<BSZ, 256>>>(out_p);
    pv_kernel<<<dim3(EMB / BN, SEQ / BM, BATCH), 256>>>(out_p, out_z);
}

// round 2
// speedup vs baseline: 2.0709x; 2.0709x over previous
#include <cuda_runtime.h>
#include <math.h>
#include <stdint.h>

#define NEGINF -1000000.0f

// Problem constants
#define BATCH 8
#define SEQ   2048
#define EMB   512
#define BSZ   (BATCH * SEQ)   // 16384 rows total

// Scratch: Q, K, V projections (fp32). __device__ globals (no allocs allowed).
__device__ float g_Q[(size_t)BSZ * EMB];
__device__ float g_K[(size_t)BSZ * EMB];
__device__ float g_V[(size_t)BSZ * EMB];

// Tiling: block 128x128, BK=16, 8 warps (2 x 4), warp tile 64x32.
#define BM 128
#define BN 128
#define BK 16
#define PAD 4

__device__ __forceinline__ uint32_t f2tf(float f) {
    uint32_t r;
    asm("cvt.rna.tf32.f32 %0, %1;" : "=r"(r) : "f"(f));
    return r;
}

__device__ __forceinline__ void mma_tf32(float (&d)[4], const uint32_t (&a)[4],
                                         const uint32_t (&b)[2]) {
    asm volatile(
        "mma.sync.aligned.m16n8k8.row.col.f32.tf32.tf32.f32 "
        "{%0,%1,%2,%3}, {%4,%5,%6,%7}, {%8,%9}, {%0,%1,%2,%3};\n"
        : "+f"(d[0]), "+f"(d[1]), "+f"(d[2]), "+f"(d[3])
        : "r"(a[0]), "r"(a[1]), "r"(a[2]), "r"(a[3]), "r"(b[0]), "r"(b[1]));
}

// Shared GEMM body pieces are expanded per-kernel (different operand layouts
// and epilogues); all use:
//   As[k][m] (A transposed into smem), Bs[k][n], both tf32 bit patterns.

// ---------------------------------------------------------------------------
// Kernel 1: projections. C = alpha * A[M,512] @ W[512,512]; z picks Q/K/V.
// ---------------------------------------------------------------------------
__global__ __launch_bounds__(256)
void proj_kernel(const float* __restrict__ Xq, const float* __restrict__ Xk,
                 const float* __restrict__ Xv, const float* __restrict__ Wq,
                 const float* __restrict__ Wk, const float* __restrict__ Wv,
                 float inv_scale)
{
    const float* A; const float* W; float* C; float alpha;
    int z = blockIdx.z;
    if (z == 0)      { A = Xq; W = Wq; C = g_Q; alpha = inv_scale; }
    else if (z == 1) { A = Xk; W = Wk; C = g_K; alpha = inv_scale; }
    else             { A = Xv; W = Wv; C = g_V; alpha = 1.0f; }

    const int K = 512, N = 512;

    __shared__ uint32_t As[BK][BM + PAD];
    __shared__ uint32_t Bs[BK][BN + PAD];

    int tid = threadIdx.x;
    int wid = tid >> 5, lane = tid & 31;
    int gid = lane >> 2, tig = lane & 3;
    int wm = wid >> 2, wn = wid & 3;        // 2 x 4 warp grid
    int m0 = blockIdx.y * BM, n0 = blockIdx.x * BN;

    int arow = tid >> 2;            // 0..63
    int acol = (tid & 3) << 2;      // 0,4,8,12
    int brow = tid >> 5;            // 0..7
    int bcol = (tid & 31) << 2;     // 0..124

    float acc[4][4][4];
#pragma unroll
    for (int i = 0; i < 4; i++)
#pragma unroll
        for (int j = 0; j < 4; j++)
#pragma unroll
            for (int r = 0; r < 4; r++) acc[i][j][r] = 0.f;

    for (int k0 = 0; k0 < K; k0 += BK) {
#pragma unroll
        for (int p = 0; p < 2; p++) {
            float4 v = *(const float4*)&A[(size_t)(m0 + arow + p * 64) * K + k0 + acol];
            As[acol + 0][arow + p * 64] = f2tf(v.x);
            As[acol + 1][arow + p * 64] = f2tf(v.y);
            As[acol + 2][arow + p * 64] = f2tf(v.z);
            As[acol + 3][arow + p * 64] = f2tf(v.w);
        }
#pragma unroll
        for (int p = 0; p < 2; p++) {
            float4 v = *(const float4*)&W[(size_t)(k0 + brow + p * 8) * N + n0 + bcol];
            Bs[brow + p * 8][bcol + 0] = f2tf(v.x);
            Bs[brow + p * 8][bcol + 1] = f2tf(v.y);
            Bs[brow + p * 8][bcol + 2] = f2tf(v.z);
            Bs[brow + p * 8][bcol + 3] = f2tf(v.w);
        }
        __syncthreads();
#pragma unroll
        for (int ks = 0; ks < 2; ks++) {
            int kk = ks * 8;
            uint32_t af[4][4], bf[4][2];
#pragma unroll
            for (int mi = 0; mi < 4; mi++) {
                int m = wm * 64 + mi * 16 + gid;
                af[mi][0] = As[kk + tig][m];
                af[mi][1] = As[kk + tig][m + 8];
                af[mi][2] = As[kk + tig + 4][m];
                af[mi][3] = As[kk + tig + 4][m + 8];
            }
#pragma unroll
            for (int ni = 0; ni < 4; ni++) {
                int n = wn * 32 + ni * 8 + gid;
                bf[ni][0] = Bs[kk + tig][n];
                bf[ni][1] = Bs[kk + tig + 4][n];
            }
#pragma unroll
            for (int mi = 0; mi < 4; mi++)
#pragma unroll
                for (int ni = 0; ni < 4; ni++)
                    mma_tf32(acc[mi][ni], af[mi], bf[ni]);
        }
        __syncthreads();
    }

#pragma unroll
    for (int mi = 0; mi < 4; mi++) {
        int r = m0 + wm * 64 + mi * 16 + gid;
#pragma unroll
        for (int ni = 0; ni < 4; ni++) {
            int c = n0 + wn * 32 + ni * 8 + tig * 2;
            *(float2*)&C[(size_t)r * N + c] =
                make_float2(acc[mi][ni][0] * alpha, acc[mi][ni][1] * alpha);
            *(float2*)&C[(size_t)(r + 8) * N + c] =
                make_float2(acc[mi][ni][2] * alpha, acc[mi][ni][3] * alpha);
        }
    }
}

// ---------------------------------------------------------------------------
// Kernel 2: masked scores. logits = Q Kt, NEGINF where mask==0. Per batch.
// ---------------------------------------------------------------------------
__global__ __launch_bounds__(256)
void scores_kernel(const int* __restrict__ mask, float* __restrict__ out_p)
{
    const int K = 512;
    int b = blockIdx.z;
    const float* Qb = g_Q + (size_t)b * SEQ * EMB;
    const float* Kb = g_K + (size_t)b * SEQ * EMB;
    const int*  Mb  = mask + (size_t)b * SEQ * SEQ;
    float*      Cb  = out_p + (size_t)b * SEQ * SEQ;

    __shared__ uint32_t As[BK][BM + PAD];
    __shared__ uint32_t Bs[BK][BN + PAD];

    int tid = threadIdx.x;
    int wid = tid >> 5, lane = tid & 31;
    int gid = lane >> 2, tig = lane & 3;
    int wm = wid >> 2, wn = wid & 3;
    int m0 = blockIdx.y * BM, n0 = blockIdx.x * BN;

    int arow = tid >> 2;
    int acol = (tid & 3) << 2;

    float acc[4][4][4];
#pragma unroll
    for (int i = 0; i < 4; i++)
#pragma unroll
        for (int j = 0; j < 4; j++)
#pragma unroll
            for (int r = 0; r < 4; r++) acc[i][j][r] = 0.f;

    for (int k0 = 0; k0 < K; k0 += BK) {
#pragma unroll
        for (int p = 0; p < 2; p++) {
            float4 v = *(const float4*)&Qb[(size_t)(m0 + arow + p * 64) * K + k0 + acol];
            As[acol + 0][arow + p * 64] = f2tf(v.x);
            As[acol + 1][arow + p * 64] = f2tf(v.y);
            As[acol + 2][arow + p * 64] = f2tf(v.z);
            As[acol + 3][arow + p * 64] = f2tf(v.w);
        }
        // Bs[k][n] = Kb[n0+n][k0+k]  (transposed staging)
#pragma unroll
        for (int p = 0; p < 2; p++) {
            float4 v = *(const float4*)&Kb[(size_t)(n0 + arow + p * 64) * K + k0 + acol];
            Bs[acol + 0][arow + p * 64] = f2tf(v.x);
            Bs[acol + 1][arow + p * 64] = f2tf(v.y);
            Bs[acol + 2][arow + p * 64] = f2tf(v.z);
            Bs[acol + 3][arow + p * 64] = f2tf(v.w);
        }
        __syncthreads();
#pragma unroll
        for (int ks = 0; ks < 2; ks++) {
            int kk = ks * 8;
            uint32_t af[4][4], bf[4][2];
#pragma unroll
            for (int mi = 0; mi < 4; mi++) {
                int m = wm * 64 + mi * 16 + gid;
                af[mi][0] = As[kk + tig][m];
                af[mi][1] = As[kk + tig][m + 8];
                af[mi][2] = As[kk + tig + 4][m];
                af[mi][3] = As[kk + tig + 4][m + 8];
            }
#pragma unroll
            for (int ni = 0; ni < 4; ni++) {
                int n = wn * 32 + ni * 8 + gid;
                bf[ni][0] = Bs[kk + tig][n];
                bf[ni][1] = Bs[kk + tig + 4][n];
            }
#pragma unroll
            for (int mi = 0; mi < 4; mi++)
#pragma unroll
                for (int ni = 0; ni < 4; ni++)
                    mma_tf32(acc[mi][ni], af[mi], bf[ni]);
        }
        __syncthreads();
    }

#pragma unroll
    for (int mi = 0; mi < 4; mi++) {
        int r = m0 + wm * 64 + mi * 16 + gid;
#pragma unroll
        for (int ni = 0; ni < 4; ni++) {
            int c = n0 + wn * 32 + ni * 8 + tig * 2;
            size_t o0 = (size_t)r * SEQ + c;
            size_t o1 = (size_t)(r + 8) * SEQ + c;
            int2 mv0 = *(const int2*)&Mb[o0];
            int2 mv1 = *(const int2*)&Mb[o1];
            *(float2*)&Cb[o0] = make_float2(mv0.x ? acc[mi][ni][0] : NEGINF,
                                            mv0.y ? acc[mi][ni][1] : NEGINF);
            *(float2*)&Cb[o1] = make_float2(mv1.x ? acc[mi][ni][2] : NEGINF,
                                            mv1.y ? acc[mi][ni][3] : NEGINF);
        }
    }
}

// ---------------------------------------------------------------------------
// Kernel 3: row softmax (in place). Masked = NEGINF -> exactly 0.
// ---------------------------------------------------------------------------
__global__ __launch_bounds__(256)
void softmax_kernel(float* __restrict__ P)
{
    float* prow = P + (size_t)blockIdx.x * SEQ;
    int tid = threadIdx.x;
    int lane = tid & 31, warp = tid >> 5;
    __shared__ float red[8];

    float4 v0 = ((const float4*)prow)[tid];
    float4 v1 = ((const float4*)prow)[tid + 256];
    float x[8] = {v0.x, v0.y, v0.z, v0.w, v1.x, v1.y, v1.z, v1.w};

    float m = x[0];
#pragma unroll
    for (int i = 1; i < 8; i++) m = fmaxf(m, x[i]);
#pragma unroll
    for (int o = 16; o > 0; o >>= 1) m = fmaxf(m, __shfl_xor_sync(0xFFFFFFFFu, m, o));
    if (lane == 0) red[warp] = m;
    __syncthreads();
    m = red[0];
#pragma unroll
    for (int i = 1; i < 8; i++) m = fmaxf(m, red[i]);

    if (m == NEGINF) {  // fully masked row
        float4 z = make_float4(0.f, 0.f, 0.f, 0.f);
        ((float4*)prow)[tid] = z;
        ((float4*)prow)[tid + 256] = z;
        return;
    }

    float e[8], s = 0.f;
#pragma unroll
    for (int i = 0; i < 8; i++) { e[i] = __expf(x[i] - m); s += e[i]; }
#pragma unroll
    for (int o = 16; o > 0; o >>= 1) s += __shfl_xor_sync(0xFFFFFFFFu, s, o);
    __syncthreads();
    if (lane == 0) red[warp] = s;
    __syncthreads();
    s = 0.f;
#pragma unroll
    for (int i = 0; i < 8; i++) s += red[i];
    float inv = 1.0f / s;

    ((float4*)prow)[tid]       = make_float4(e[0] * inv, e[1] * inv, e[2] * inv, e[3] * inv);
    ((float4*)prow)[tid + 256] = make_float4(e[4] * inv, e[5] * inv, e[6] * inv, e[7] * inv);
}

// ---------------------------------------------------------------------------
// Kernel 4: z = P @ V per batch. M=2048, N=512, K=2048.
// ---------------------------------------------------------------------------
__global__ __launch_bounds__(256)
void pv_kernel(const float* __restrict__ P, float* __restrict__ out_z)
{
    const int K = SEQ, N = EMB;
    int b = blockIdx.z;
    const float* Ab = P + (size_t)b * SEQ * SEQ;
    const float* Vb = g_V + (size_t)b * SEQ * EMB;
    float*       Cb = out_z + (size_t)b * SEQ * EMB;

    __shared__ uint32_t As[BK][BM + PAD];
    __shared__ uint32_t Bs[BK][BN + PAD];

    int tid = threadIdx.x;
    int wid = tid >> 5, lane = tid & 31;
    int gid = lane >> 2, tig = lane & 3;
    int wm = wid >> 2, wn = wid & 3;
    int m0 = blockIdx.y * BM, n0 = blockIdx.x * BN;

    int arow = tid >> 2;
    int acol = (tid & 3) << 2;
    int brow = tid >> 5;
    int bcol = (tid & 31) << 2;

    float acc[4][4][4];
#pragma unroll
    for (int i = 0; i < 4; i++)
#pragma unroll
        for (int j = 0; j < 4; j++)
#pragma unroll
            for (int r = 0; r < 4; r++) acc[i][j][r] = 0.f;

    for (int k0 = 0; k0 < K; k0 += BK) {
#pragma unroll
        for (int p = 0; p < 2; p++) {
            float4 v = *(const float4*)&Ab[(size_t)(m0 + arow + p * 64) * K + k0 + acol];
            As[acol + 0][arow + p * 64] = f2tf(v.x);
            As[acol + 1][arow + p * 64] = f2tf(v.y);
            As[acol + 2][arow + p * 64] = f2tf(v.z);
            As[acol + 3][arow + p * 64] = f2tf(v.w);
        }
#pragma unroll
        for (int p = 0; p < 2; p++) {
            float4 v = *(const float4*)&Vb[(size_t)(k0 + brow + p * 8) * N + n0 + bcol];
            Bs[brow + p * 8][bcol + 0] = f2tf(v.x);
            Bs[brow + p * 8][bcol + 1] = f2tf(v.y);
            Bs[brow + p * 8][bcol + 2] = f2tf(v.z);
            Bs[brow + p * 8][bcol + 3] = f2tf(v.w);
        }
        __syncthreads();
#pragma unroll
        for (int ks = 0; ks < 2; ks++) {
            int kk = ks * 8;
            uint32_t af[4][4], bf[4][2];
#pragma unroll
            for (int mi = 0; mi < 4; mi++) {
                int m = wm * 64 + mi * 16 + gid;
                af[mi][0] = As[kk + tig][m];
                af[mi][1] = As[kk + tig][m + 8];
                af[mi][2] = As[kk + tig + 4][m];
                af[mi][3] = As[kk + tig + 4][m + 8];
            }
#pragma unroll
            for (int ni = 0; ni < 4; ni++) {
                int n = wn * 32 + ni * 8 + gid;
                bf[ni][0] = Bs[kk + tig][n];
                bf[ni][1] = Bs[kk + tig + 4][n];
            }
#pragma unroll
            for (int mi = 0; mi < 4; mi++)
#pragma unroll
                for (int ni = 0; ni < 4; ni++)
                    mma_tf32(acc[mi][ni], af[mi], bf[ni]);
        }
        __syncthreads();
    }

#pragma unroll
    for (int mi = 0; mi < 4; mi++) {
        int r = m0 + wm * 64 + mi * 16 + gid;
#pragma unroll
        for (int ni = 0; ni < 4; ni++) {
            int c = n0 + wn * 32 + ni * 8 + tig * 2;
            *(float2*)&Cb[(size_t)r * N + c] = make_float2(acc[mi][ni][0], acc[mi][ni][1]);
            *(float2*)&Cb[(size_t)(r + 8) * N + c] = make_float2(acc[mi][ni][2], acc[mi][ni][3]);
        }
    }
}

// ---------------------------------------------------------------------------
// Launch. Inputs: Xin_q, Xin_k, Xin_v, mask, Wq, Wk, Wv.
// Output: z [8,2048,512] then attn_p [8,2048,2048], fp32.
// ---------------------------------------------------------------------------
extern "C" void kernel_launch(void* const* d_in, const int* in_sizes, int n_in,
                              void* d_out, int out_size)
{
    const float* Xq = (const float*)d_in[0];
    const float* Xk = (const float*)d_in[1];
    const float* Xv = (const float*)d_in[2];
    const int*   mk = (const int*)d_in[3];
    const float* Wq = (const float*)d_in[4];
    const float* Wk = (const float*)d_in[5];
    const float* Wv = (const float*)d_in[6];

    float* out_z = (float*)d_out;
    float* out_p = out_z + (size_t)BATCH * SEQ * EMB;

    const float inv_scale = 0.21022410381342864f;  // 1/512^(1/4)

    proj_kernel<<<dim3(EMB / BN, BSZ / BM, 3), 256>>>(Xq, Xk, Xv, Wq, Wk, Wv, inv_scale);
    scores_kernel<<<dim3(SEQ / BN, SEQ / BM, BATCH), 256>>>(mk, out_p);
    softmax_kernel<<<BSZ, 256>>>(out_p);
    pv_kernel<<<dim3(EMB / BN, SEQ / BM, BATCH), 256>>>(out_p, out_z);
}

// round 5
// speedup vs baseline: 2.2756x; 1.0988x over previous
#include <cuda_runtime.h>
#include <math.h>
#include <stdint.h>

#define NEGINF -1000000.0f

// Problem constants
#define BATCH 8
#define SEQ   2048
#define EMB   512
#define BSZ   (BATCH * SEQ)

// Scratch: Q, K, V projections (fp32). __device__ globals (no allocs allowed).
__device__ float g_Q[(size_t)BSZ * EMB];
__device__ float g_K[(size_t)BSZ * EMB];
__device__ float g_V[(size_t)BSZ * EMB];

// Tiling: block 128x128, BK=16 double-buffered, 8 warps (2x4), warp tile 64x32.
#define BM 128
#define BN 128
#define BK 16
#define PAD 4

__device__ __forceinline__ uint32_t f2tf(float f) {
    uint32_t r;
    asm("cvt.rna.tf32.f32 %0, %1;" : "=r"(r) : "f"(f));
    return r;
}

__device__ __forceinline__ void mma_tf32(float (&d)[4], const uint32_t (&a)[4],
                                         const uint32_t (&b)[2]) {
    asm volatile(
        "mma.sync.aligned.m16n8k8.row.col.f32.tf32.tf32.f32 "
        "{%0,%1,%2,%3}, {%4,%5,%6,%7}, {%8,%9}, {%0,%1,%2,%3};\n"
        : "+f"(d[0]), "+f"(d[1]), "+f"(d[2]), "+f"(d[3])
        : "r"(a[0]), "r"(a[1]), "r"(a[2]), "r"(a[3]), "r"(b[0]), "r"(b[1]));
}

// Compute one BK=16 chunk from smem buffers (shared by all 3 GEMM kernels).
#define COMPUTE_CHUNK(AsBuf, BsBuf)                                          \
    do {                                                                     \
        _Pragma("unroll")                                                    \
        for (int ks = 0; ks < 2; ks++) {                                     \
            int kk = ks * 8;                                                 \
            uint32_t af[4][4], bf[4][2];                                     \
            _Pragma("unroll")                                                \
            for (int mi = 0; mi < 4; mi++) {                                 \
                int m = wm * 64 + mi * 16 + gid;                             \
                af[mi][0] = (AsBuf)[kk + tig][m];                            \
                af[mi][1] = (AsBuf)[kk + tig][m + 8];                        \
                af[mi][2] = (AsBuf)[kk + tig + 4][m];                        \
                af[mi][3] = (AsBuf)[kk + tig + 4][m + 8];                    \
            }                                                                \
            _Pragma("unroll")                                                \
            for (int ni = 0; ni < 4; ni++) {                                 \
                int n = wn * 32 + ni * 8 + gid;                              \
                bf[ni][0] = (BsBuf)[kk + tig][n];                            \
                bf[ni][1] = (BsBuf)[kk + tig + 4][n];                        \
            }                                                                \
            _Pragma("unroll")                                                \
            for (int mi = 0; mi < 4; mi++)                                   \
                _Pragma("unroll")                                            \
                for (int ni = 0; ni < 4; ni++)                               \
                    mma_tf32(acc[mi][ni], af[mi], bf[ni]);                   \
        }                                                                    \
    } while (0)

// ---------------------------------------------------------------------------
// Kernel 1: projections. C = alpha * A[M,512] @ W[512,512]; z picks Q/K/V.
// ---------------------------------------------------------------------------
__global__ __launch_bounds__(256, 2)
void proj_kernel(const float* __restrict__ Xq, const float* __restrict__ Xk,
                 const float* __restrict__ Xv, const float* __restrict__ Wq,
                 const float* __restrict__ Wk, const float* __restrict__ Wv,
                 float inv_scale)
{
    const float* A; const float* W; float* C; float alpha;
    int z = blockIdx.z;
    if (z == 0)      { A = Xq; W = Wq; C = g_Q; alpha = inv_scale; }
    else if (z == 1) { A = Xk; W = Wk; C = g_K; alpha = inv_scale; }
    else             { A = Xv; W = Wv; C = g_V; alpha = 1.0f; }

    const int K = 512, N = 512;

    __shared__ uint32_t As[2][BK][BM + PAD];
    __shared__ uint32_t Bs[2][BK][BN + PAD];

    int tid = threadIdx.x;
    int wid = tid >> 5, lane = tid & 31;
    int gid = lane >> 2, tig = lane & 3;
    int wm = wid >> 2, wn = wid & 3;
    int m0 = blockIdx.y * BM, n0 = blockIdx.x * BN;

    int arow = tid >> 2;            // 0..63
    int acol = (tid & 3) << 2;      // 0,4,8,12
    int brow = tid >> 5;            // 0..7
    int bcol = (tid & 31) << 2;     // 0..124

    float acc[4][4][4];
#pragma unroll
    for (int i = 0; i < 4; i++)
#pragma unroll
        for (int j = 0; j < 4; j++)
#pragma unroll
            for (int r = 0; r < 4; r++) acc[i][j][r] = 0.f;

    float4 ra[2], rb[2];
#define PROJ_LDG(k0)                                                          \
    do {                                                                      \
        ra[0] = *(const float4*)&A[(size_t)(m0 + arow) * K + (k0) + acol];    \
        ra[1] = *(const float4*)&A[(size_t)(m0 + arow + 64) * K + (k0) + acol]; \
        rb[0] = *(const float4*)&W[(size_t)((k0) + brow) * N + n0 + bcol];    \
        rb[1] = *(const float4*)&W[(size_t)((k0) + brow + 8) * N + n0 + bcol]; \
    } while (0)
#define PROJ_STS(buf)                                                         \
    do {                                                                      \
        _Pragma("unroll")                                                     \
        for (int p = 0; p < 2; p++) {                                         \
            As[buf][acol + 0][arow + p * 64] = f2tf(ra[p].x);                 \
            As[buf][acol + 1][arow + p * 64] = f2tf(ra[p].y);                 \
            As[buf][acol + 2][arow + p * 64] = f2tf(ra[p].z);                 \
            As[buf][acol + 3][arow + p * 64] = f2tf(ra[p].w);                 \
            uint4 u = make_uint4(f2tf(rb[p].x), f2tf(rb[p].y),                \
                                 f2tf(rb[p].z), f2tf(rb[p].w));               \
            *(uint4*)&Bs[buf][brow + p * 8][bcol] = u;                        \
        }                                                                     \
    } while (0)

    PROJ_LDG(0);
    PROJ_STS(0);
    __syncthreads();

    const int iters = K / BK;
    for (int it = 0; it < iters; it++) {
        int cur = it & 1;
        bool more = (it + 1 < iters);
        if (more) PROJ_LDG((it + 1) * BK);
        COMPUTE_CHUNK(As[cur], Bs[cur]);
        if (more) PROJ_STS(cur ^ 1);
        __syncthreads();
    }
#undef PROJ_LDG
#undef PROJ_STS

#pragma unroll
    for (int mi = 0; mi < 4; mi++) {
        int r = m0 + wm * 64 + mi * 16 + gid;
#pragma unroll
        for (int ni = 0; ni < 4; ni++) {
            int c = n0 + wn * 32 + ni * 8 + tig * 2;
            *(float2*)&C[(size_t)r * N + c] =
                make_float2(acc[mi][ni][0] * alpha, acc[mi][ni][1] * alpha);
            *(float2*)&C[(size_t)(r + 8) * N + c] =
                make_float2(acc[mi][ni][2] * alpha, acc[mi][ni][3] * alpha);
        }
    }
}

// ---------------------------------------------------------------------------
// Kernel 2: masked scores. logits = Q Kt, NEGINF where mask==0. Per batch.
// ---------------------------------------------------------------------------
__global__ __launch_bounds__(256, 2)
void scores_kernel(const int* __restrict__ mask, float* __restrict__ out_p)
{
    const int K = 512;
    int b = blockIdx.z;
    const float* Qb = g_Q + (size_t)b * SEQ * EMB;
    const float* Kb = g_K + (size_t)b * SEQ * EMB;
    const int*  Mb  = mask + (size_t)b * SEQ * SEQ;
    float*      Cb  = out_p + (size_t)b * SEQ * SEQ;

    __shared__ uint32_t As[2][BK][BM + PAD];
    __shared__ uint32_t Bs[2][BK][BN + PAD];

    int tid = threadIdx.x;
    int wid = tid >> 5, lane = tid & 31;
    int gid = lane >> 2, tig = lane & 3;
    int wm = wid >> 2, wn = wid & 3;
    int m0 = blockIdx.y * BM, n0 = blockIdx.x * BN;

    int arow = tid >> 2;
    int acol = (tid & 3) << 2;

    float acc[4][4][4];
#pragma unroll
    for (int i = 0; i < 4; i++)
#pragma unroll
        for (int j = 0; j < 4; j++)
#pragma unroll
            for (int r = 0; r < 4; r++) acc[i][j][r] = 0.f;

    float4 ra[2], rb[2];
#define SC_LDG(k0)                                                            \
    do {                                                                      \
        ra[0] = *(const float4*)&Qb[(size_t)(m0 + arow) * K + (k0) + acol];   \
        ra[1] = *(const float4*)&Qb[(size_t)(m0 + arow + 64) * K + (k0) + acol]; \
        rb[0] = *(const float4*)&Kb[(size_t)(n0 + arow) * K + (k0) + acol];   \
        rb[1] = *(const float4*)&Kb[(size_t)(n0 + arow + 64) * K + (k0) + acol]; \
    } while (0)
#define SC_STS(buf)                                                           \
    do {                                                                      \
        _Pragma("unroll")                                                     \
        for (int p = 0; p < 2; p++) {                                         \
            As[buf][acol + 0][arow + p * 64] = f2tf(ra[p].x);                 \
            As[buf][acol + 1][arow + p * 64] = f2tf(ra[p].y);                 \
            As[buf][acol + 2][arow + p * 64] = f2tf(ra[p].z);                 \
            As[buf][acol + 3][arow + p * 64] = f2tf(ra[p].w);                 \
            Bs[buf][acol + 0][arow + p * 64] = f2tf(rb[p].x);                 \
            Bs[buf][acol + 1][arow + p * 64] = f2tf(rb[p].y);                 \
            Bs[buf][acol + 2][arow + p * 64] = f2tf(rb[p].z);                 \
            Bs[buf][acol + 3][arow + p * 64] = f2tf(rb[p].w);                 \
        }                                                                     \
    } while (0)

    SC_LDG(0);
    SC_STS(0);
    __syncthreads();

    const int iters = K / BK;
    for (int it = 0; it < iters; it++) {
        int cur = it & 1;
        bool more = (it + 1 < iters);
        if (more) SC_LDG((it + 1) * BK);
        COMPUTE_CHUNK(As[cur], Bs[cur]);
        if (more) SC_STS(cur ^ 1);
        __syncthreads();
    }
#undef SC_LDG
#undef SC_STS

#pragma unroll
    for (int mi = 0; mi < 4; mi++) {
        int r = m0 + wm * 64 + mi * 16 + gid;
#pragma unroll
        for (int ni = 0; ni < 4; ni++) {
            int c = n0 + wn * 32 + ni * 8 + tig * 2;
            size_t o0 = (size_t)r * SEQ + c;
            size_t o1 = (size_t)(r + 8) * SEQ + c;
            int2 mv0 = *(const int2*)&Mb[o0];
            int2 mv1 = *(const int2*)&Mb[o1];
            *(float2*)&Cb[o0] = make_float2(mv0.x ? acc[mi][ni][0] : NEGINF,
                                            mv0.y ? acc[mi][ni][1] : NEGINF);
            *(float2*)&Cb[o1] = make_float2(mv1.x ? acc[mi][ni][2] : NEGINF,
                                            mv1.y ? acc[mi][ni][3] : NEGINF);
        }
    }
}

// ---------------------------------------------------------------------------
// Kernel 3: row softmax (in place). Masked = NEGINF -> exactly 0.
// ---------------------------------------------------------------------------
__global__ __launch_bounds__(256)
void softmax_kernel(float* __restrict__ P)
{
    float* prow = P + (size_t)blockIdx.x * SEQ;
    int tid = threadIdx.x;
    int lane = tid & 31, warp = tid >> 5;
    __shared__ float red[8];

    float4 v0 = ((const float4*)prow)[tid];
    float4 v1 = ((const float4*)prow)[tid + 256];
    float x[8] = {v0.x, v0.y, v0.z, v0.w, v1.x, v1.y, v1.z, v1.w};

    float m = x[0];
#pragma unroll
    for (int i = 1; i < 8; i++) m = fmaxf(m, x[i]);
#pragma unroll
    for (int o = 16; o > 0; o >>= 1) m = fmaxf(m, __shfl_xor_sync(0xFFFFFFFFu, m, o));
    if (lane == 0) red[warp] = m;
    __syncthreads();
    m = red[0];
#pragma unroll
    for (int i = 1; i < 8; i++) m = fmaxf(m, red[i]);

    if (m == NEGINF) {  // fully masked row
        float4 zz = make_float4(0.f, 0.f, 0.f, 0.f);
        ((float4*)prow)[tid] = zz;
        ((float4*)prow)[tid + 256] = zz;
        return;
    }

    float e[8], s = 0.f;
#pragma unroll
    for (int i = 0; i < 8; i++) { e[i] = __expf(x[i] - m); s += e[i]; }
#pragma unroll
    for (int o = 16; o > 0; o >>= 1) s += __shfl_xor_sync(0xFFFFFFFFu, s, o);
    __syncthreads();
    if (lane == 0) red[warp] = s;
    __syncthreads();
    s = 0.f;
#pragma unroll
    for (int i = 0; i < 8; i++) s += red[i];
    float inv = 1.0f / s;

    ((float4*)prow)[tid]       = make_float4(e[0] * inv, e[1] * inv, e[2] * inv, e[3] * inv);
    ((float4*)prow)[tid + 256] = make_float4(e[4] * inv, e[5] * inv, e[6] * inv, e[7] * inv);
}

// ---------------------------------------------------------------------------
// Kernel 4: z = P @ V per batch. M=2048, N=512, K=2048.
// ---------------------------------------------------------------------------
__global__ __launch_bounds__(256, 2)
void pv_kernel(const float* __restrict__ P, float* __restrict__ out_z)
{
    const int K = SEQ, N = EMB;
    int b = blockIdx.z;
    const float* Ab = P + (size_t)b * SEQ * SEQ;
    const float* Vb = g_V + (size_t)b * SEQ * EMB;
    float*       Cb = out_z + (size_t)b * SEQ * EMB;

    __shared__ uint32_t As[2][BK][BM + PAD];
    __shared__ uint32_t Bs[2][BK][BN + PAD];

    int tid = threadIdx.x;
    int wid = tid >> 5, lane = tid & 31;
    int gid = lane >> 2, tig = lane & 3;
    int wm = wid >> 2, wn = wid & 3;
    int m0 = blockIdx.y * BM, n0 = blockIdx.x * BN;

    int arow = tid >> 2;
    int acol = (tid & 3) << 2;
    int brow = tid >> 5;
    int bcol = (tid & 31) << 2;

    float acc[4][4][4];
#pragma unroll
    for (int i = 0; i < 4; i++)
#pragma unroll
        for (int j = 0; j < 4; j++)
#pragma unroll
            for (int r = 0; r < 4; r++) acc[i][j][r] = 0.f;

    float4 ra[2], rb[2];
#define PV_LDG(k0)                                                            \
    do {                                                                      \
        ra[0] = *(const float4*)&Ab[(size_t)(m0 + arow) * K + (k0) + acol];   \
        ra[1] = *(const float4*)&Ab[(size_t)(m0 + arow + 64) * K + (k0) + acol]; \
        rb[0] = *(const float4*)&Vb[(size_t)((k0) + brow) * N + n0 + bcol];   \
        rb[1] = *(const float4*)&Vb[(size_t)((k0) + brow + 8) * N + n0 + bcol]; \
    } while (0)
#define PV_STS(buf)                                                           \
    do {                                                                      \
        _Pragma("unroll")                                                     \
        for (int p = 0; p < 2; p++) {                                         \
            As[buf][acol + 0][arow + p * 64] = f2tf(ra[p].x);                 \
            As[buf][acol + 1][arow + p * 64] = f2tf(ra[p].y);                 \
            As[buf][acol + 2][arow + p * 64] = f2tf(ra[p].z);                 \
            As[buf][acol + 3][arow + p * 64] = f2tf(ra[p].w);                 \
            uint4 u = make_uint4(f2tf(rb[p].x), f2tf(rb[p].y),                \
                                 f2tf(rb[p].z), f2tf(rb[p].w));               \
            *(uint4*)&Bs[buf][brow + p * 8][bcol] = u;                        \
        }                                                                     \
    } while (0)

    PV_LDG(0);
    PV_STS(0);
    __syncthreads();

    const int iters = K / BK;
    for (int it = 0; it < iters; it++) {
        int cur = it & 1;
        bool more = (it + 1 < iters);
        if (more) PV_LDG((it + 1) * BK);
        COMPUTE_CHUNK(As[cur], Bs[cur]);
        if (more) PV_STS(cur ^ 1);
        __syncthreads();
    }
#undef PV_LDG
#undef PV_STS

#pragma unroll
    for (int mi = 0; mi < 4; mi++) {
        int r = m0 + wm * 64 + mi * 16 + gid;
#pragma unroll
        for (int ni = 0; ni < 4; ni++) {
            int c = n0 + wn * 32 + ni * 8 + tig * 2;
            *(float2*)&Cb[(size_t)r * N + c] = make_float2(acc[mi][ni][0], acc[mi][ni][1]);
            *(float2*)&Cb[(size_t)(r + 8) * N + c] = make_float2(acc[mi][ni][2], acc[mi][ni][3]);
        }
    }
}

// ---------------------------------------------------------------------------
// Launch. Inputs: Xin_q, Xin_k, Xin_v, mask, Wq, Wk, Wv.
// Output: z [8,2048,512] then attn_p [8,2048,2048], fp32.
// ---------------------------------------------------------------------------
extern "C" void kernel_launch(void* const* d_in, const int* in_sizes, int n_in,
                              void* d_out, int out_size)
{
    const float* Xq = (const float*)d_in[0];
    const float* Xk = (const float*)d_in[1];
    const float* Xv = (const float*)d_in[2];
    const int*   mk = (const int*)d_in[3];
    const float* Wq = (const float*)d_in[4];
    const float* Wk = (const float*)d_in[5];
    const float* Wv = (const float*)d_in[6];

    float* out_z = (float*)d_out;
    float* out_p = out_z + (size_t)BATCH * SEQ * EMB;

    const float inv_scale = 0.21022410381342864f;  // 1/512^(1/4)

    proj_kernel<<<dim3(EMB / BN, BSZ / BM, 3), 256>>>(Xq, Xk, Xv, Wq, Wk, Wv, inv_scale);
    scores_kernel<<<dim3(SEQ / BN, SEQ / BM, BATCH), 256>>>(mk, out_p);
    softmax_kernel<<<BSZ, 256>>>(out_p);
    pv_kernel<<<dim3(EMB / BN, SEQ / BM, BATCH), 256>>>(out_p, out_z);
}